// round 5
// baseline (speedup 1.0000x reference)
#include <cuda_runtime.h>
#include <cuda_bf16.h>

#define Bn 8
#define Hn 56
#define Wn 56
#define Cn 64
#define Nn (Hn*Wn)      // 3136
#define En 64
#define NSPLIT 2
#define TPS 49          // TK=32 tiles per split (98 total / 2)

// Q full fp32 (pre-scaled by 8). K/V split to bf16 hi/lo, packed in pairs
// along the MMA k-dimension:
//   K: [b][c/2][n]  (pair of channels per bfloat162)  - B operand of Q K^T
//   V: [b][n/2][c]  (pair of keys per bfloat162)      - B operand of P V
__device__ float    g_Q  [Bn*Nn*Cn];
__device__ unsigned g_Khi[Bn*(Cn/2)*Nn];
__device__ unsigned g_Klo[Bn*(Cn/2)*Nn];
__device__ unsigned g_Vhi[Bn*(Nn/2)*Cn];
__device__ unsigned g_Vlo[Bn*(Nn/2)*Cn];
// Split-K partials: unnormalized O and row-sum l per split
__device__ float    g_Op [NSPLIT*Bn*Nn*Cn];   // 12.8 MB
__device__ float    g_Lp [NSPLIT*Bn*Nn];

// ---------------------------------------------------------------------------
// Kernel 1: depthwise 3x3 conv for q, k, v; K/V written split+packed.
// ---------------------------------------------------------------------------
__global__ __launch_bounds__(256) void qkv_conv_kernel(
    const float* __restrict__ x,
    const float* __restrict__ wq, const float* __restrict__ bq,
    const float* __restrict__ wk, const float* __restrict__ bk,
    const float* __restrict__ wv, const float* __restrict__ bv)
{
    __shared__ float swq[9*Cn], swk[9*Cn], swv[9*Cn];
    const int b = blockIdx.x / Hn;
    const int h = blockIdx.x % Hn;
    for (int i = threadIdx.x; i < 9*Cn; i += blockDim.x) {
        swq[i] = wq[i]; swk[i] = wk[i]; swv[i] = wv[i];
    }
    __syncthreads();

    for (int idx = threadIdx.x; idx < Wn*Cn; idx += blockDim.x) {
        const int w = idx / Cn;
        const int c = idx % Cn;
        float aq = bq[c], ak = bk[c], av = bv[c];
        #pragma unroll
        for (int dh = 0; dh < 3; dh++) {
            const int hh = h + dh - 1;
            if (hh < 0 || hh >= Hn) continue;
            #pragma unroll
            for (int dw = 0; dw < 3; dw++) {
                const int ww = w + dw - 1;
                if (ww < 0 || ww >= Wn) continue;
                const float xv = x[((b*Hn + hh)*Wn + ww)*Cn + c];
                const int wi = (dh*3 + dw)*Cn + c;
                aq = fmaf(swq[wi], xv, aq);
                ak = fmaf(swk[wi], xv, ak);
                av = fmaf(swv[wi], xv, av);
            }
        }
        const int n = h*Wn + w;
        g_Q[((size_t)b*Nn + n)*Cn + c] = aq * 8.0f;   // fold score scale (pow2)

        {   // K split: hi/lo bf16, element (pair c>>1, key n, slot c&1)
            __nv_bfloat16 hb = __float2bfloat16(ak);
            __nv_bfloat16 lb = __float2bfloat16(ak - __bfloat162float(hb));
            const size_t e = ((size_t)b*(Cn/2)*Nn + (size_t)(c >> 1)*Nn + n)*2 + (c & 1);
            ((__nv_bfloat16*)g_Khi)[e] = hb;
            ((__nv_bfloat16*)g_Klo)[e] = lb;
        }
        {   // V split: element (pair n>>1, chan c, slot n&1)
            __nv_bfloat16 hb = __float2bfloat16(av);
            __nv_bfloat16 lb = __float2bfloat16(av - __bfloat162float(hb));
            const size_t e = ((size_t)b*(Nn/2)*Cn + (size_t)(n >> 1)*Cn + c)*2 + (n & 1);
            ((__nv_bfloat16*)g_Vhi)[e] = hb;
            ((__nv_bfloat16*)g_Vlo)[e] = lb;
        }
    }
}

// ---------------------------------------------------------------------------
#define MMA(d, a, b0, b1) \
  asm volatile("mma.sync.aligned.m16n8k16.row.col.f32.bf16.bf16.f32 " \
    "{%0,%1,%2,%3}, {%4,%5,%6,%7}, {%8,%9}, {%0,%1,%2,%3};" \
    : "+f"(d[0]), "+f"(d[1]), "+f"(d[2]), "+f"(d[3]) \
    : "r"(a[0]), "r"(a[1]), "r"(a[2]), "r"(a[3]), "r"(b0), "r"(b1))

__device__ __forceinline__ void bsplit2(float vx, float vy, unsigned& h, unsigned& l) {
    __nv_bfloat162 H = __floats2bfloat162_rn(vx, vy);
    float2 hf = __bfloat1622float2(H);
    __nv_bfloat162 L = __floats2bfloat162_rn(vx - hf.x, vy - hf.y);
    h = *(unsigned*)&H;
    l = *(unsigned*)&L;
}

__device__ __forceinline__ void cpa16(unsigned* dst, const uint4* src) {
    unsigned s = (unsigned)__cvta_generic_to_shared(dst);
    asm volatile("cp.async.cg.shared.global [%0], [%1], 16;" :: "r"(s), "l"(src));
}

// ---------------------------------------------------------------------------
// Kernel 2: split-K flash attention partials (no-max softmax), bf16x3 MMA.
// grid (49, 8, 2), 128 threads (4 warps), TK=32, double-buffered cp.async.
// Writes unnormalized O and row-sums l; linear merge is exact (no max).
// ---------------------------------------------------------------------------
__global__ __launch_bounds__(128, 4) void attn_partial_kernel()
{
    extern __shared__ unsigned smem[];   // 2 x 4096: [Khi 1024|Klo 1024|Vhi 1024|Vlo 1024]

    const int b    = blockIdx.y;
    const int q0   = blockIdx.x * 64;
    const int sp   = blockIdx.z;
    const int tid  = threadIdx.x;
    const int wp   = tid >> 5;
    const int lane = tid & 31;
    const int gr   = lane >> 2;   // 0..7
    const int q    = lane & 3;    // 0..3

    // ---- Q fragments (hi/lo), rows 16wp+{gr,gr+8}, resident all tiles ----
    const float* Qb = g_Q + ((size_t)(b*Nn + q0 + 16*wp))*Cn;
    unsigned aQh[4][4], aQl[4][4];
    #pragma unroll
    for (int ks = 0; ks < 4; ks++) {
        const float* r0 = Qb + gr*64;
        const float* r1 = Qb + (gr + 8)*64;
        float2 v;
        v = *(const float2*)(r0 + 16*ks + 2*q);     bsplit2(v.x, v.y, aQh[ks][0], aQl[ks][0]);
        v = *(const float2*)(r1 + 16*ks + 2*q);     bsplit2(v.x, v.y, aQh[ks][1], aQl[ks][1]);
        v = *(const float2*)(r0 + 16*ks + 8 + 2*q); bsplit2(v.x, v.y, aQh[ks][2], aQl[ks][2]);
        v = *(const float2*)(r1 + 16*ks + 8 + 2*q); bsplit2(v.x, v.y, aQh[ks][3], aQl[ks][3]);
    }

    float oA[8][4];
    #pragma unroll
    for (int j = 0; j < 8; j++)
        #pragma unroll
        for (int i = 0; i < 4; i++) oA[j][i] = 0.0f;
    float l0 = 0.0f, l1 = 0.0f;

    const uint4* gKh = (const uint4*)(g_Khi + (size_t)b*(Cn/2)*Nn);
    const uint4* gKl = (const uint4*)(g_Klo + (size_t)b*(Cn/2)*Nn);
    const uint4* gVh = (const uint4*)(g_Vhi + (size_t)b*(Nn/2)*Cn);
    const uint4* gVl = (const uint4*)(g_Vlo + (size_t)b*(Nn/2)*Cn);

    const int kt0 = sp * TPS;

    // TK=32 tile: K 32 chanpairs x 32 keys; V 16 keypairs x 64 chans (hi+lo)
    auto issue_tile = [&](int kt, int bufsel) {
        unsigned* base = smem + bufsel*4096;
        #pragma unroll
        for (int it = 0; it < 2; it++) {
            const int f  = tid + it*128;
            const int pr = f >> 3, cg = f & 7;
            const int sw = (4*cg) ^ ((pr & 3) << 3);
            const int kidx = pr*(Nn/4) + kt*8 + cg;
            cpa16(&base[       pr*32 + sw], gKh + kidx);
            cpa16(&base[1024 + pr*32 + sw], gKl + kidx);
        }
        #pragma unroll
        for (int it = 0; it < 2; it++) {
            const int f  = tid + it*128;
            const int vp = f >> 4, cg = f & 15;
            const int sw = (4*cg) ^ ((vp & 3) << 3);
            const int vidx = (kt*16 + vp)*(Cn/4) + cg;
            cpa16(&base[2048 + vp*64 + sw], gVh + vidx);
            cpa16(&base[3072 + vp*64 + sw], gVl + vidx);
        }
        asm volatile("cp.async.commit_group;" ::: "memory");
    };

    issue_tile(kt0, 0);
    int buf = 0;

    for (int t = 0; t < TPS; t++) {
        asm volatile("cp.async.wait_group 0;" ::: "memory");
        __syncthreads();
        if (t + 1 < TPS) issue_tile(kt0 + t + 1, buf ^ 1);

        const unsigned* sKhi = smem + buf*4096;
        const unsigned* sKlo = sKhi + 1024;
        const unsigned* sVhi = sKhi + 2048;
        const unsigned* sVlo = sKhi + 3072;

        // ---- S = Q K^T (3-product bf16, products issued as j-sweeps) ----
        float sA[4][4];
        #pragma unroll
        for (int j = 0; j < 4; j++)
            #pragma unroll
            for (int i = 0; i < 4; i++) sA[j][i] = 0.0f;
        #pragma unroll
        for (int ks = 0; ks < 4; ks++) {
            const unsigned* kh0 = &sKhi[(8*ks + q    )*32];
            const unsigned* kh1 = &sKhi[(8*ks + 4 + q)*32];
            const unsigned* kl0 = &sKlo[(8*ks + q    )*32];
            const unsigned* kl1 = &sKlo[(8*ks + 4 + q)*32];
            unsigned bh0[4], bh1[4], bl0[4], bl1[4];
            #pragma unroll
            for (int j = 0; j < 4; j++) {
                const int col = (8*j + gr) ^ (q << 3);
                bh0[j] = kh0[col]; bh1[j] = kh1[col];
                bl0[j] = kl0[col]; bl1[j] = kl1[col];
            }
            #pragma unroll
            for (int j = 0; j < 4; j++) MMA(sA[j], aQh[ks], bh0[j], bh1[j]);
            #pragma unroll
            for (int j = 0; j < 4; j++) MMA(sA[j], aQl[ks], bh0[j], bh1[j]);
            #pragma unroll
            for (int j = 0; j < 4; j++) MMA(sA[j], aQh[ks], bl0[j], bl1[j]);
        }

        // ---- plain exp (scores bounded well under fp32 overflow) ----
        #pragma unroll
        for (int j = 0; j < 4; j++) {
            sA[j][0] = __expf(sA[j][0]);
            sA[j][1] = __expf(sA[j][1]);
            sA[j][2] = __expf(sA[j][2]);
            sA[j][3] = __expf(sA[j][3]);
            l0 += sA[j][0] + sA[j][1];
            l1 += sA[j][2] + sA[j][3];
        }

        // ---- O += P V : P fragments from accumulator identity ----
        #pragma unroll
        for (int kp = 0; kp < 2; kp++) {
            unsigned aPh[4], aPl[4];
            bsplit2(sA[2*kp    ][0], sA[2*kp    ][1], aPh[0], aPl[0]);
            bsplit2(sA[2*kp    ][2], sA[2*kp    ][3], aPh[1], aPl[1]);
            bsplit2(sA[2*kp + 1][0], sA[2*kp + 1][1], aPh[2], aPl[2]);
            bsplit2(sA[2*kp + 1][2], sA[2*kp + 1][3], aPh[3], aPl[3]);
            const unsigned* vh0 = &sVhi[(8*kp + q    )*64];
            const unsigned* vh1 = &sVhi[(8*kp + 4 + q)*64];
            const unsigned* vl0 = &sVlo[(8*kp + q    )*64];
            const unsigned* vl1 = &sVlo[(8*kp + 4 + q)*64];
            #pragma unroll
            for (int jg = 0; jg < 2; jg++) {
                unsigned vbh0[4], vbh1[4], vbl0[4], vbl1[4];
                #pragma unroll
                for (int j4 = 0; j4 < 4; j4++) {
                    const int col = (8*(jg*4 + j4) + gr) ^ (q << 3);
                    vbh0[j4] = vh0[col]; vbh1[j4] = vh1[col];
                    vbl0[j4] = vl0[col]; vbl1[j4] = vl1[col];
                }
                #pragma unroll
                for (int j4 = 0; j4 < 4; j4++) MMA(oA[jg*4 + j4], aPh, vbh0[j4], vbh1[j4]);
                #pragma unroll
                for (int j4 = 0; j4 < 4; j4++) MMA(oA[jg*4 + j4], aPl, vbh0[j4], vbh1[j4]);
                #pragma unroll
                for (int j4 = 0; j4 < 4; j4++) MMA(oA[jg*4 + j4], aPh, vbl0[j4], vbl1[j4]);
            }
        }

        buf ^= 1;
    }

    // ---- write partials: unnormalized O rows + quad-reduced l ----
    l0 += __shfl_xor_sync(0xffffffffu, l0, 1);
    l0 += __shfl_xor_sync(0xffffffffu, l0, 2);
    l1 += __shfl_xor_sync(0xffffffffu, l1, 1);
    l1 += __shfl_xor_sync(0xffffffffu, l1, 2);

    const size_t rowbase = ((size_t)sp*Bn + b)*Nn + q0 + 16*wp;
    if (q == 0) {
        g_Lp[rowbase + gr    ] = l0;
        g_Lp[rowbase + gr + 8] = l1;
    }
    float* Or0 = g_Op + (rowbase + gr)*Cn;
    float* Or1 = Or0 + 8*Cn;
    #pragma unroll
    for (int j = 0; j < 8; j++) {
        *(float2*)&Or0[8*j + 2*q] = make_float2(oA[j][0], oA[j][1]);
        *(float2*)&Or1[8*j + 2*q] = make_float2(oA[j][2], oA[j][3]);
    }
}

// ---------------------------------------------------------------------------
// Kernel 3: combine splits + projection. grid (49, 8), 128 threads.
// ctx = (O0+O1)/(l0+l1); out = ctx @ Wp + bp  (bf16x3 MMA, Wp in smem)
// ---------------------------------------------------------------------------
__global__ __launch_bounds__(128) void combine_kernel(
    const float* __restrict__ Wp, const float* __restrict__ bp,
    float* __restrict__ out)
{
    __shared__ unsigned sWh[2048], sWl[2048];   // 32 chanpairs x 64, swizzled

    const int b    = blockIdx.y;
    const int q0   = blockIdx.x * 64;
    const int tid  = threadIdx.x;
    const int wp   = tid >> 5;
    const int lane = tid & 31;
    const int gr   = lane >> 2;
    const int q    = lane & 3;

    for (int i = tid; i < 4096; i += 128) {
        const int c = i >> 6, e = i & 63;
        const int pr = c >> 1;
        const float wv = Wp[i];
        __nv_bfloat16 hb = __float2bfloat16(wv);
        __nv_bfloat16 lb = __float2bfloat16(wv - __bfloat162float(hb));
        const int col = e ^ ((pr & 3) << 3);
        ((__nv_bfloat16*)sWh)[(pr*64 + col)*2 + (c & 1)] = hb;
        ((__nv_bfloat16*)sWl)[(pr*64 + col)*2 + (c & 1)] = lb;
    }
    __syncthreads();

    const size_t r0 = (size_t)b*Nn + q0 + 16*wp + gr;   // within one split
    const size_t r1 = r0 + 8;
    const float inv0 = 1.0f / (g_Lp[r0] + g_Lp[(size_t)Bn*Nn + r0]);
    const float inv1 = 1.0f / (g_Lp[r1] + g_Lp[(size_t)Bn*Nn + r1]);

    const float* O0r0 = g_Op + r0*Cn;
    const float* O0r1 = g_Op + r1*Cn;
    const float* O1r0 = O0r0 + (size_t)Bn*Nn*Cn;
    const float* O1r1 = O0r1 + (size_t)Bn*Nn*Cn;

    float c0[8][2], c1[8][2];
    #pragma unroll
    for (int j = 0; j < 8; j++) {
        float2 a = *(const float2*)&O0r0[8*j + 2*q];
        float2 d = *(const float2*)&O1r0[8*j + 2*q];
        c0[j][0] = (a.x + d.x)*inv0;  c0[j][1] = (a.y + d.y)*inv0;
        a = *(const float2*)&O0r1[8*j + 2*q];
        d = *(const float2*)&O1r1[8*j + 2*q];
        c1[j][0] = (a.x + d.x)*inv1;  c1[j][1] = (a.y + d.y)*inv1;
    }

    float pA[8][4];
    #pragma unroll
    for (int j = 0; j < 8; j++)
        #pragma unroll
        for (int i = 0; i < 4; i++) pA[j][i] = 0.0f;

    #pragma unroll
    for (int ks = 0; ks < 4; ks++) {
        unsigned aCh[4], aCl[4];
        bsplit2(c0[2*ks    ][0], c0[2*ks    ][1], aCh[0], aCl[0]);
        bsplit2(c1[2*ks    ][0], c1[2*ks    ][1], aCh[1], aCl[1]);
        bsplit2(c0[2*ks + 1][0], c0[2*ks + 1][1], aCh[2], aCl[2]);
        bsplit2(c1[2*ks + 1][0], c1[2*ks + 1][1], aCh[3], aCl[3]);
        const unsigned* wh0 = &sWh[(8*ks + q    )*64];
        const unsigned* wh1 = &sWh[(8*ks + 4 + q)*64];
        const unsigned* wl0 = &sWl[(8*ks + q    )*64];
        const unsigned* wl1 = &sWl[(8*ks + 4 + q)*64];
        #pragma unroll
        for (int jg = 0; jg < 2; jg++) {
            unsigned bh0[4], bh1[4], bl0[4], bl1[4];
            #pragma unroll
            for (int j4 = 0; j4 < 4; j4++) {
                const int col = (8*(jg*4 + j4) + gr) ^ (q << 3);
                bh0[j4] = wh0[col]; bh1[j4] = wh1[col];
                bl0[j4] = wl0[col]; bl1[j4] = wl1[col];
            }
            #pragma unroll
            for (int j4 = 0; j4 < 4; j4++) MMA(pA[jg*4 + j4], aCh, bh0[j4], bh1[j4]);
            #pragma unroll
            for (int j4 = 0; j4 < 4; j4++) MMA(pA[jg*4 + j4], aCl, bh0[j4], bh1[j4]);
            #pragma unroll
            for (int j4 = 0; j4 < 4; j4++) MMA(pA[jg*4 + j4], aCh, bl0[j4], bl1[j4]);
        }
    }

    float* orow0 = out + r0*En;
    float* orow1 = out + r1*En;
    #pragma unroll
    for (int j = 0; j < 8; j++) {
        const float2 bv = *(const float2*)&bp[8*j + 2*q];
        *(float2*)&orow0[8*j + 2*q] = make_float2(pA[j][0] + bv.x, pA[j][1] + bv.y);
        *(float2*)&orow1[8*j + 2*q] = make_float2(pA[j][2] + bv.x, pA[j][3] + bv.y);
    }
}

// ---------------------------------------------------------------------------
extern "C" void kernel_launch(void* const* d_in, const int* in_sizes, int n_in,
                              void* d_out, int out_size)
{
    const float* x  = (const float*)d_in[0];
    const float* wq = (const float*)d_in[1];
    const float* bq = (const float*)d_in[2];
    const float* wk = (const float*)d_in[3];
    const float* bk = (const float*)d_in[4];
    const float* wv = (const float*)d_in[5];
    const float* bv = (const float*)d_in[6];
    const float* Wp = (const float*)d_in[7];
    const float* bp = (const float*)d_in[8];
    float* out = (float*)d_out;

    const int smem_bytes = 2*4096*4;   // 32 KB: double-buffered TK=32 tiles
    cudaFuncSetAttribute(attn_partial_kernel,
                         cudaFuncAttributeMaxDynamicSharedMemorySize, smem_bytes);

    qkv_conv_kernel<<<Bn*Hn, 256>>>(x, wq, bq, wk, bk, wv, bv);

    dim3 grid(Nn/64, Bn, NSPLIT);
    attn_partial_kernel<<<grid, 128, smem_bytes>>>();

    dim3 cgrid(Nn/64, Bn);
    combine_kernel<<<cgrid, 128>>>(Wp, bp, out);
}

// round 6
// speedup vs baseline: 1.1701x; 1.1701x over previous
#include <cuda_runtime.h>
#include <cuda_bf16.h>

#define Bn 8
#define Hn 56
#define Wn 56
#define Cn 64
#define Nn (Hn*Wn)      // 3136
#define En 64
#define NT 49           // 3136/64 k-tiles

// Q full fp32 (pre-scaled by 8). K/V split to bf16 hi/lo, packed in pairs
// along the MMA k-dimension:
//   K: [b][c/2][n]  (pair of channels per bfloat162)  - B operand of Q K^T
//   V: [b][n/2][c]  (pair of keys per bfloat162)      - B operand of P V
__device__ float    g_Q  [Bn*Nn*Cn];
__device__ unsigned g_Khi[Bn*(Cn/2)*Nn];
__device__ unsigned g_Klo[Bn*(Cn/2)*Nn];
__device__ unsigned g_Vhi[Bn*(Nn/2)*Cn];
__device__ unsigned g_Vlo[Bn*(Nn/2)*Cn];

// ---------------------------------------------------------------------------
// Kernel 1: depthwise 3x3 conv; row staged in smem, all global writes coalesced.
// grid = B*H, 256 threads. Dynamic smem: weights (6912B) + 3 padded rows.
// ---------------------------------------------------------------------------
#define RS 65   // row stride (floats) for staged q/k/v rows (bank-conflict pad)

__global__ __launch_bounds__(256) void qkv_conv_kernel(
    const float* __restrict__ x,
    const float* __restrict__ wq, const float* __restrict__ bq,
    const float* __restrict__ wk, const float* __restrict__ bk,
    const float* __restrict__ wv, const float* __restrict__ bv)
{
    extern __shared__ float csm[];
    float* swq = csm;                 // 9*64
    float* swk = swq + 9*Cn;
    float* swv = swk + 9*Cn;
    float* qrow = swv + 9*Cn;         // 56*65
    float* krow = qrow + Wn*RS;
    float* vrow = krow + Wn*RS;

    const int b = blockIdx.x / Hn;
    const int h = blockIdx.x % Hn;
    for (int i = threadIdx.x; i < 9*Cn; i += 256) {
        swq[i] = wq[i]; swk[i] = wk[i]; swv[i] = wv[i];
    }
    __syncthreads();

    // ---- compute conv row into smem ----
    for (int idx = threadIdx.x; idx < Wn*Cn; idx += 256) {
        const int w = idx >> 6;
        const int c = idx & 63;
        float aq = bq[c], ak = bk[c], av = bv[c];
        #pragma unroll
        for (int dh = 0; dh < 3; dh++) {
            const int hh = h + dh - 1;
            if (hh < 0 || hh >= Hn) continue;
            #pragma unroll
            for (int dw = 0; dw < 3; dw++) {
                const int ww = w + dw - 1;
                if (ww < 0 || ww >= Wn) continue;
                const float xv = x[((b*Hn + hh)*Wn + ww)*Cn + c];
                const int wi = (dh*3 + dw)*Cn + c;
                aq = fmaf(swq[wi], xv, aq);
                ak = fmaf(swk[wi], xv, ak);
                av = fmaf(swv[wi], xv, av);
            }
        }
        qrow[w*RS + c] = aq * 8.0f;   // fold score scale (pow2, exact)
        krow[w*RS + c] = ak;
        vrow[w*RS + c] = av;
    }
    __syncthreads();

    // ---- Q writer: [b][n][c], 4B coalesced ----
    {
        float* dst = g_Q + ((size_t)b*Nn + h*Wn)*Cn;
        for (int idx = threadIdx.x; idx < Wn*Cn; idx += 256)
            dst[idx] = qrow[(idx >> 6)*RS + (idx & 63)];
    }
    // ---- K writer: word (pair p, key n) = bf16x2(c=2p, c=2p+1), n-fast ----
    {
        unsigned* dh_ = g_Khi + (size_t)b*(Cn/2)*Nn + h*Wn;
        unsigned* dl_ = g_Klo + (size_t)b*(Cn/2)*Nn + h*Wn;
        for (int i = threadIdx.x; i < (Cn/2)*Wn; i += 256) {
            const int p = i / Wn;
            const int w = i % Wn;
            const float k0 = krow[w*RS + 2*p];
            const float k1 = krow[w*RS + 2*p + 1];
            __nv_bfloat162 H = __floats2bfloat162_rn(k0, k1);
            float2 hf = __bfloat1622float2(H);
            __nv_bfloat162 L = __floats2bfloat162_rn(k0 - hf.x, k1 - hf.y);
            dh_[p*Nn + w] = *(unsigned*)&H;
            dl_[p*Nn + w] = *(unsigned*)&L;
        }
    }
    // ---- V writer: word (keypair np, chan c) = bf16x2(n even, n odd), c-fast ----
    {
        unsigned* dh_ = g_Vhi + (size_t)b*(Nn/2)*Cn + (h*Wn/2)*Cn;
        unsigned* dl_ = g_Vlo + (size_t)b*(Nn/2)*Cn + (h*Wn/2)*Cn;
        for (int i = threadIdx.x; i < (Wn/2)*Cn; i += 256) {
            const int wp2 = i >> 6;          // key pair within row
            const int c   = i & 63;
            const float v0 = vrow[(2*wp2    )*RS + c];
            const float v1 = vrow[(2*wp2 + 1)*RS + c];
            __nv_bfloat162 H = __floats2bfloat162_rn(v0, v1);
            float2 hf = __bfloat1622float2(H);
            __nv_bfloat162 L = __floats2bfloat162_rn(v0 - hf.x, v1 - hf.y);
            dh_[i] = *(unsigned*)&H;
            dl_[i] = *(unsigned*)&L;
        }
    }
}

// ---------------------------------------------------------------------------
// Kernel 2: flash attention (no-max softmax) + projection, bf16x3 mma.sync.
// block = 128 threads (4 warps); warp wp owns q-rows [16wp, 16wp+16).
// grid = (49, 8). Double-buffered cp.async tiles; P/ctx stay in registers.
// MMA products issued as j-sweeps (4 independent accumulators between RAW).
// ---------------------------------------------------------------------------
#define MMA(d, a, b0, b1) \
  asm volatile("mma.sync.aligned.m16n8k16.row.col.f32.bf16.bf16.f32 " \
    "{%0,%1,%2,%3}, {%4,%5,%6,%7}, {%8,%9}, {%0,%1,%2,%3};" \
    : "+f"(d[0]), "+f"(d[1]), "+f"(d[2]), "+f"(d[3]) \
    : "r"(a[0]), "r"(a[1]), "r"(a[2]), "r"(a[3]), "r"(b0), "r"(b1))

__device__ __forceinline__ void bsplit2(float vx, float vy, unsigned& h, unsigned& l) {
    __nv_bfloat162 H = __floats2bfloat162_rn(vx, vy);
    float2 hf = __bfloat1622float2(H);
    __nv_bfloat162 L = __floats2bfloat162_rn(vx - hf.x, vy - hf.y);
    h = *(unsigned*)&H;
    l = *(unsigned*)&L;
}

__device__ __forceinline__ void cpa16(unsigned* dst, const uint4* src) {
    unsigned s = (unsigned)__cvta_generic_to_shared(dst);
    asm volatile("cp.async.cg.shared.global [%0], [%1], 16;" :: "r"(s), "l"(src));
}

__global__ __launch_bounds__(128, 3) void attn_kernel(
    const float* __restrict__ Wp, const float* __restrict__ bp,
    float* __restrict__ out)
{
    extern __shared__ unsigned smem[];   // 2 buffers x (Khi|Klo|Vhi|Vlo) x 2048

    const int b    = blockIdx.y;
    const int q0   = blockIdx.x * 64;
    const int tid  = threadIdx.x;
    const int wp   = tid >> 5;
    const int lane = tid & 31;
    const int gr   = lane >> 2;   // 0..7
    const int q    = lane & 3;    // 0..3

    // ---- Q fragments (hi/lo), rows 16wp+{gr,gr+8}, resident all tiles ----
    const float* Qb = g_Q + ((size_t)(b*Nn + q0 + 16*wp))*Cn;
    unsigned aQh[4][4], aQl[4][4];
    #pragma unroll
    for (int ks = 0; ks < 4; ks++) {
        const float* r0 = Qb + gr*64;
        const float* r1 = Qb + (gr + 8)*64;
        float2 v;
        v = *(const float2*)(r0 + 16*ks + 2*q);     bsplit2(v.x, v.y, aQh[ks][0], aQl[ks][0]);
        v = *(const float2*)(r1 + 16*ks + 2*q);     bsplit2(v.x, v.y, aQh[ks][1], aQl[ks][1]);
        v = *(const float2*)(r0 + 16*ks + 8 + 2*q); bsplit2(v.x, v.y, aQh[ks][2], aQl[ks][2]);
        v = *(const float2*)(r1 + 16*ks + 8 + 2*q); bsplit2(v.x, v.y, aQh[ks][3], aQl[ks][3]);
    }

    float oA[8][4];
    #pragma unroll
    for (int j = 0; j < 8; j++)
        #pragma unroll
        for (int i = 0; i < 4; i++) oA[j][i] = 0.0f;
    float l0 = 0.0f, l1 = 0.0f;   // per-thread partial row sums

    const uint4* gKh = (const uint4*)(g_Khi + (size_t)b*(Cn/2)*Nn);
    const uint4* gKl = (const uint4*)(g_Klo + (size_t)b*(Cn/2)*Nn);
    const uint4* gVh = (const uint4*)(g_Vhi + (size_t)b*(Nn/2)*Cn);
    const uint4* gVl = (const uint4*)(g_Vlo + (size_t)b*(Nn/2)*Cn);

    auto issue_tile = [&](int kt, int bufsel) {
        unsigned* base = smem + bufsel*8192;
        #pragma unroll
        for (int it = 0; it < 4; it++) {
            const int f  = tid + it*128;
            const int pr = f >> 4;          // 0..31
            const int cg = f & 15;
            const int sw = (4*cg) ^ ((pr & 3) << 3);
            const int kidx = pr*(Nn/4) + kt*16 + cg;
            const int vidx = (kt*32 + pr)*(Cn/4) + cg;
            cpa16(&base[       pr*64 + sw], gKh + kidx);
            cpa16(&base[2048 + pr*64 + sw], gKl + kidx);
            cpa16(&base[4096 + pr*64 + sw], gVh + vidx);
            cpa16(&base[6144 + pr*64 + sw], gVl + vidx);
        }
        asm volatile("cp.async.commit_group;" ::: "memory");
    };

    issue_tile(0, 0);
    int buf = 0;

    for (int kt = 0; kt < NT; kt++) {
        asm volatile("cp.async.wait_group 0;" ::: "memory");
        __syncthreads();                    // tile ready + prev compute done
        if (kt + 1 < NT) issue_tile(kt + 1, buf ^ 1);

        const unsigned* sKhi = smem + buf*8192;
        const unsigned* sKlo = sKhi + 2048;
        const unsigned* sVhi = sKhi + 4096;
        const unsigned* sVlo = sKhi + 6144;

        // ---- S = Q K^T (3-product bf16, j-sweep issue order) ----
        float sA[8][4];
        #pragma unroll
        for (int j = 0; j < 8; j++)
            #pragma unroll
            for (int i = 0; i < 4; i++) sA[j][i] = 0.0f;
        #pragma unroll
        for (int ks = 0; ks < 4; ks++) {
            const unsigned* kh0 = &sKhi[(8*ks + q    )*64];
            const unsigned* kh1 = &sKhi[(8*ks + 4 + q)*64];
            const unsigned* kl0 = &sKlo[(8*ks + q    )*64];
            const unsigned* kl1 = &sKlo[(8*ks + 4 + q)*64];
            #pragma unroll
            for (int jg = 0; jg < 2; jg++) {
                unsigned bh0[4], bh1[4], bl0[4], bl1[4];
                #pragma unroll
                for (int j4 = 0; j4 < 4; j4++) {
                    const int col = (8*(jg*4 + j4) + gr) ^ (q << 3);
                    bh0[j4] = kh0[col]; bh1[j4] = kh1[col];
                    bl0[j4] = kl0[col]; bl1[j4] = kl1[col];
                }
                float* acc = &sA[jg*4][0];
                #pragma unroll
                for (int j4 = 0; j4 < 4; j4++) MMA((&acc[4*j4]), aQh[ks], bh0[j4], bh1[j4]);
                #pragma unroll
                for (int j4 = 0; j4 < 4; j4++) MMA((&acc[4*j4]), aQl[ks], bh0[j4], bh1[j4]);
                #pragma unroll
                for (int j4 = 0; j4 < 4; j4++) MMA((&acc[4*j4]), aQh[ks], bl0[j4], bl1[j4]);
            }
        }

        // ---- softmax numerator: plain exp (scores bounded ~|30| << 88) ----
        #pragma unroll
        for (int j = 0; j < 8; j++) {
            sA[j][0] = __expf(sA[j][0]);
            sA[j][1] = __expf(sA[j][1]);
            sA[j][2] = __expf(sA[j][2]);
            sA[j][3] = __expf(sA[j][3]);
            l0 += sA[j][0] + sA[j][1];
            l1 += sA[j][2] + sA[j][3];
        }

        // ---- O += P V : P fragments from accumulator identity, j-sweeps ----
        #pragma unroll
        for (int ks = 0; ks < 4; ks++) {
            unsigned aPh[4], aPl[4];
            bsplit2(sA[2*ks    ][0], sA[2*ks    ][1], aPh[0], aPl[0]);
            bsplit2(sA[2*ks    ][2], sA[2*ks    ][3], aPh[1], aPl[1]);
            bsplit2(sA[2*ks + 1][0], sA[2*ks + 1][1], aPh[2], aPl[2]);
            bsplit2(sA[2*ks + 1][2], sA[2*ks + 1][3], aPh[3], aPl[3]);
            const unsigned* vh0 = &sVhi[(8*ks + q    )*64];
            const unsigned* vh1 = &sVhi[(8*ks + 4 + q)*64];
            const unsigned* vl0 = &sVlo[(8*ks + q    )*64];
            const unsigned* vl1 = &sVlo[(8*ks + 4 + q)*64];
            #pragma unroll
            for (int jg = 0; jg < 2; jg++) {
                unsigned vbh0[4], vbh1[4], vbl0[4], vbl1[4];
                #pragma unroll
                for (int j4 = 0; j4 < 4; j4++) {
                    const int col = (8*(jg*4 + j4) + gr) ^ (q << 3);
                    vbh0[j4] = vh0[col]; vbh1[j4] = vh1[col];
                    vbl0[j4] = vl0[col]; vbl1[j4] = vl1[col];
                }
                #pragma unroll
                for (int j4 = 0; j4 < 4; j4++) MMA(oA[jg*4 + j4], aPh, vbh0[j4], vbh1[j4]);
                #pragma unroll
                for (int j4 = 0; j4 < 4; j4++) MMA(oA[jg*4 + j4], aPl, vbh0[j4], vbh1[j4]);
                #pragma unroll
                for (int j4 = 0; j4 < 4; j4++) MMA(oA[jg*4 + j4], aPh, vbl0[j4], vbl1[j4]);
            }
        }

        buf ^= 1;
    }

    // ============= epilogue: ctx = O/l; out = ctx @ Wp + bp =============
    l0 += __shfl_xor_sync(0xffffffffu, l0, 1);
    l0 += __shfl_xor_sync(0xffffffffu, l0, 2);
    l1 += __shfl_xor_sync(0xffffffffu, l1, 1);
    l1 += __shfl_xor_sync(0xffffffffu, l1, 2);
    const float inv0 = 1.0f / l0;
    const float inv1 = 1.0f / l1;

    __syncthreads();                        // all compute done, smem reusable
    unsigned* sWh = smem;
    unsigned* sWl = smem + 2048;
    for (int i = tid; i < 4096; i += 128) {
        const int c = i >> 6, e = i & 63;
        const int pr = c >> 1;
        const float wv = Wp[i];
        __nv_bfloat16 hb = __float2bfloat16(wv);
        __nv_bfloat16 lb = __float2bfloat16(wv - __bfloat162float(hb));
        const int col = e ^ ((pr & 3) << 3);
        ((__nv_bfloat16*)sWh)[(pr*64 + col)*2 + (c & 1)] = hb;
        ((__nv_bfloat16*)sWl)[(pr*64 + col)*2 + (c & 1)] = lb;
    }
    __syncthreads();

    float pA[8][4];
    #pragma unroll
    for (int j = 0; j < 8; j++)
        #pragma unroll
        for (int i = 0; i < 4; i++) pA[j][i] = 0.0f;
    #pragma unroll
    for (int ks = 0; ks < 4; ks++) {
        unsigned aCh[4], aCl[4];
        bsplit2(oA[2*ks    ][0]*inv0, oA[2*ks    ][1]*inv0, aCh[0], aCl[0]);
        bsplit2(oA[2*ks    ][2]*inv1, oA[2*ks    ][3]*inv1, aCh[1], aCl[1]);
        bsplit2(oA[2*ks + 1][0]*inv0, oA[2*ks + 1][1]*inv0, aCh[2], aCl[2]);
        bsplit2(oA[2*ks + 1][2]*inv1, oA[2*ks + 1][3]*inv1, aCh[3], aCl[3]);
        const unsigned* wh0 = &sWh[(8*ks + q    )*64];
        const unsigned* wh1 = &sWh[(8*ks + 4 + q)*64];
        const unsigned* wl0 = &sWl[(8*ks + q    )*64];
        const unsigned* wl1 = &sWl[(8*ks + 4 + q)*64];
        #pragma unroll
        for (int jg = 0; jg < 2; jg++) {
            unsigned bh0[4], bh1[4], bl0[4], bl1[4];
            #pragma unroll
            for (int j4 = 0; j4 < 4; j4++) {
                const int col = (8*(jg*4 + j4) + gr) ^ (q << 3);
                bh0[j4] = wh0[col]; bh1[j4] = wh1[col];
                bl0[j4] = wl0[col]; bl1[j4] = wl1[col];
            }
            #pragma unroll
            for (int j4 = 0; j4 < 4; j4++) MMA(pA[jg*4 + j4], aCh, bh0[j4], bh1[j4]);
            #pragma unroll
            for (int j4 = 0; j4 < 4; j4++) MMA(pA[jg*4 + j4], aCl, bh0[j4], bh1[j4]);
            #pragma unroll
            for (int j4 = 0; j4 < 4; j4++) MMA(pA[jg*4 + j4], aCh, bl0[j4], bl1[j4]);
        }
    }

    float* orow0 = out + (size_t)(b*Nn + q0 + 16*wp + gr)*En;
    float* orow1 = orow0 + 8*En;
    #pragma unroll
    for (int j = 0; j < 8; j++) {
        const float2 bv = *(const float2*)&bp[8*j + 2*q];
        *(float2*)&orow0[8*j + 2*q] = make_float2(pA[j][0] + bv.x, pA[j][1] + bv.y);
        *(float2*)&orow1[8*j + 2*q] = make_float2(pA[j][2] + bv.x, pA[j][3] + bv.y);
    }
}

// ---------------------------------------------------------------------------
extern "C" void kernel_launch(void* const* d_in, const int* in_sizes, int n_in,
                              void* d_out, int out_size)
{
    const float* x  = (const float*)d_in[0];
    const float* wq = (const float*)d_in[1];
    const float* bq = (const float*)d_in[2];
    const float* wk = (const float*)d_in[3];
    const float* bk = (const float*)d_in[4];
    const float* wv = (const float*)d_in[5];
    const float* bv = (const float*)d_in[6];
    const float* Wp = (const float*)d_in[7];
    const float* bp = (const float*)d_in[8];
    float* out = (float*)d_out;

    const int conv_smem = (27*Cn + 3*Wn*RS) * 4;   // 6912 + 43680 = 50592
    cudaFuncSetAttribute(qkv_conv_kernel,
                         cudaFuncAttributeMaxDynamicSharedMemorySize, conv_smem);
    const int smem_bytes = 2*8192*4;   // 65536: double-buffered K/V hi/lo
    cudaFuncSetAttribute(attn_kernel,
                         cudaFuncAttributeMaxDynamicSharedMemorySize, smem_bytes);

    qkv_conv_kernel<<<Bn*Hn, 256, conv_smem>>>(x, wq, bq, wk, bk, wv, bv);

    dim3 grid(NT, Bn);
    attn_kernel<<<grid, 128, smem_bytes>>>(Wp, bp, out);
}